// round 14
// baseline (speedup 1.0000x reference)
#include <cuda_runtime.h>
#include <cuda_bf16.h>
#include <cstdint>

// Problem constants
#define NB 32      // batch
#define TT 512     // time steps
#define DD 512     // input dim
#define HH 1024    // hidden dim
#define GG 3072    // 3*H

#define NCTA 128   // persistent grid
#define GTHR 128   // threads per recurrence CTA (4 warps)

// Scratch (module-load allocated; no runtime alloc)
__device__ float g_gates[(size_t)NB * TT * GG];  // 16384 x 3072
__device__ float g_zr[NB * 2 * HH];              // z region used (cols 0..1023)
__device__ unsigned g_rmask[TT];                 // per-step reset bitmasks

// bf16 hi/lo exchange buffers (uint32 = packed bf16 col-pair) — these ARE the
// mma.sync A-fragment layout: reg = pair at (row, kpair).
__device__ uint32_t g_hh[NB * 512];   // h(t) hi
__device__ uint32_t g_hl[NB * 512];   // h(t) lo
__device__ uint32_t g_rhh[NB * 512];  // rh hi
__device__ uint32_t g_rhl[NB * 512];  // rh lo
__device__ uint32_t g_h0h[512];       // h0 hi
__device__ uint32_t g_h0l[512];       // h0 lo

// split-precision bf16 operands for the gates GEMM
__device__ __nv_bfloat16 g_xhi[(size_t)NB * TT * DD];
__device__ __nv_bfloat16 g_xlo[(size_t)NB * TT * DD];
__device__ __nv_bfloat16 g_whi[(size_t)GG * DD];   // transposed [n][k]
__device__ __nv_bfloat16 g_wlo[(size_t)GG * DD];

// Hierarchical barrier state (zeroed by epilogue BEFORE gru each replay)
__device__ unsigned g_leaf[16];
__device__ unsigned g_root;
__device__ unsigned g_release;

__device__ __forceinline__ uint32_t smem_u32(const void* p)
{
    uint32_t a;
    asm("{ .reg .u64 t; cvta.to.shared.u64 t, %1; cvt.u32.u64 %0, t; }"
        : "=r"(a) : "l"(p));
    return a;
}

// ldmatrix x4 (four 8x8 b16 tiles)
#define LDSM_X4(r, a) \
    asm volatile("ldmatrix.sync.aligned.m8n8.x4.shared.b16 {%0,%1,%2,%3}, [%4];" \
        : "=r"((r)[0]), "=r"((r)[1]), "=r"((r)[2]), "=r"((r)[3]) : "r"(a))

// bf16 m16n8k16 mma, f32 accum
#define MMA_BF16(c, a, b0, b1) \
    asm volatile("mma.sync.aligned.m16n8k16.row.col.f32.bf16.bf16.f32 " \
        "{%0,%1,%2,%3}, {%4,%5,%6,%7}, {%8,%9}, {%0,%1,%2,%3};" \
        : "+f"((c)[0]), "+f"((c)[1]), "+f"((c)[2]), "+f"((c)[3]) \
        : "r"((a)[0]), "r"((a)[1]), "r"((a)[2]), "r"((a)[3]), "r"(b0), "r"(b1))

// split float2 -> packed bf16 hi/lo uint32s
__device__ __forceinline__ void split2(float2 v, uint32_t& hi, uint32_t& lo)
{
    __nv_bfloat162 h2 = __floats2bfloat162_rn(v.x, v.y);
    float2 hf = __bfloat1622float2(h2);
    __nv_bfloat162 l2 = __floats2bfloat162_rn(v.x - hf.x, v.y - hf.y);
    hi = *(uint32_t*)&h2;
    lo = *(uint32_t*)&l2;
}

__device__ __forceinline__ float2 join2(uint32_t hi, uint32_t lo)
{
    float2 h = __bfloat1622float2(*(__nv_bfloat162*)&hi);
    float2 l = __bfloat1622float2(*(__nv_bfloat162*)&lo);
    return make_float2(h.x + l.x, h.y + l.y);
}

// A-fragment direct gmem load: 4 regs = (r0,kp),(r1,kp),(r0,kp+4),(r1,kp+4)
__device__ __forceinline__ void loadA4(uint32_t* A,
    const uint32_t* __restrict__ p0, const uint32_t* __restrict__ p1, int kp)
{
    A[0] = __ldcg(&p0[kp]);
    A[1] = __ldcg(&p1[kp]);
    A[2] = __ldcg(&p0[kp + 4]);
    A[3] = __ldcg(&p1[kp + 4]);
}

// ---------------------------------------------------------------------------
// Prep: detect reset dtype (bool8 vs int32), build per-step bitmasks.
// ---------------------------------------------------------------------------
__global__ void prep_reset(const unsigned char* __restrict__ raw)
{
    __shared__ int s_bool8;
    int tid = threadIdx.x;
    if (tid == 0) s_bool8 = 0;
    __syncthreads();
    for (int i = tid; i < 4096; i += blockDim.x)
        if ((i & 3) != 0 && raw[i] != 0) s_bool8 = 1;
    __syncthreads();
    bool b8 = (s_bool8 != 0);
    const int* r32 = (const int*)raw;
    for (int t = tid; t < TT; t += blockDim.x) {
        unsigned m = 0;
        for (int b = 0; b < NB; b++) {
            bool rv = b8 ? (raw[b * TT + t] != 0) : (r32[b * TT + t] != 0);
            if (rv) m |= (1u << b);
        }
        if (t == 0) m = 0xFFFFFFFFu;
        g_rmask[t] = m;
    }
}

// ---------------------------------------------------------------------------
// Split-precision conversion kernels (gates GEMM inputs)
// ---------------------------------------------------------------------------
__global__ void conv_x(const float* __restrict__ x)
{
    int i = blockIdx.x * blockDim.x + threadIdx.x;
    if (i < NB * TT * DD) {
        float v = x[i];
        __nv_bfloat16 h = __float2bfloat16(v);
        g_xhi[i] = h;
        g_xlo[i] = __float2bfloat16(v - __bfloat162float(h));
    }
}

__global__ void conv_w(const float* __restrict__ w)
{
    int i = blockIdx.x * blockDim.x + threadIdx.x;
    if (i < DD * GG) {
        int k = i / GG;
        int n = i % GG;
        float v = w[i];
        __nv_bfloat16 h = __float2bfloat16(v);
        g_whi[(size_t)n * DD + k] = h;
        g_wlo[(size_t)n * DD + k] = __float2bfloat16(v - __bfloat162float(h));
    }
}

// ---------------------------------------------------------------------------
// Tensor-core gates GEMM (unchanged from R10 — validated, 435us)
// ---------------------------------------------------------------------------
#define ASTR 40

__global__ __launch_bounds__(256) void mma_gates(const float* __restrict__ bias)
{
    __shared__ __nv_bfloat16 sAh[128][ASTR];
    __shared__ __nv_bfloat16 sAl[128][ASTR];
    __shared__ __nv_bfloat16 sBh[128][ASTR];
    __shared__ __nv_bfloat16 sBl[128][ASTR];

    const int tid = threadIdx.x;
    const int lane = tid & 31;
    const int wid = tid >> 5;
    const int wm = wid & 1;
    const int wn = wid >> 1;
    const int bn = blockIdx.x * 128;
    const int bm = blockIdx.y * 128;

    float c[4][4][4];
#pragma unroll
    for (int i = 0; i < 4; i++)
#pragma unroll
        for (int j = 0; j < 4; j++)
#pragma unroll
            for (int q = 0; q < 4; q++) c[i][j][q] = 0.0f;

    const int a_row = wm * 64 + (lane & 7) + ((lane >> 3) & 1) * 8;
    const int a_col = ((lane >> 4) & 1) * 8;
    const int b_row = wn * 32 + (lane & 7) + ((lane >> 4) & 1) * 8;
    const int b_col = ((lane >> 3) & 1) * 8;

    for (int kc = 0; kc < 16; kc++) {
        for (int i = tid; i < 512; i += 256) {
            int row = i >> 2;
            int c8 = (i & 3) * 8;
            size_t ga = (size_t)(bm + row) * DD + kc * 32 + c8;
            size_t gb = (size_t)(bn + row) * DD + kc * 32 + c8;
            *(uint4*)&sAh[row][c8] = *(const uint4*)&g_xhi[ga];
            *(uint4*)&sAl[row][c8] = *(const uint4*)&g_xlo[ga];
            *(uint4*)&sBh[row][c8] = *(const uint4*)&g_whi[gb];
            *(uint4*)&sBl[row][c8] = *(const uint4*)&g_wlo[gb];
        }
        __syncthreads();

#pragma unroll
        for (int ks = 0; ks < 2; ks++) {
            const int k0 = ks * 16;
            uint32_t ah[4][4], al[4][4], bh[2][4], bl[2][4];
#pragma unroll
            for (int mi = 0; mi < 4; mi++) {
                uint32_t adr = smem_u32(&sAh[a_row + mi * 16][k0 + a_col]);
                LDSM_X4(ah[mi], adr);
                adr = smem_u32(&sAl[a_row + mi * 16][k0 + a_col]);
                LDSM_X4(al[mi], adr);
            }
#pragma unroll
            for (int j = 0; j < 2; j++) {
                uint32_t adr = smem_u32(&sBh[b_row + j * 16][k0 + b_col]);
                LDSM_X4(bh[j], adr);
                adr = smem_u32(&sBl[b_row + j * 16][k0 + b_col]);
                LDSM_X4(bl[j], adr);
            }
#pragma unroll
            for (int mi = 0; mi < 4; mi++) {
#pragma unroll
                for (int nj = 0; nj < 4; nj++) {
                    int j = nj >> 1, p = (nj & 1) * 2;
                    MMA_BF16(c[mi][nj], ah[mi], bh[j][p], bh[j][p + 1]);
                    MMA_BF16(c[mi][nj], ah[mi], bl[j][p], bl[j][p + 1]);
                    MMA_BF16(c[mi][nj], al[mi], bh[j][p], bh[j][p + 1]);
                }
            }
        }
        __syncthreads();
    }

#pragma unroll
    for (int mi = 0; mi < 4; mi++) {
#pragma unroll
        for (int nj = 0; nj < 4; nj++) {
            int r = bm + wm * 64 + mi * 16 + (lane >> 2);
            int cn = bn + wn * 32 + nj * 8 + (lane & 3) * 2;
            float b0 = bias[cn], b1 = bias[cn + 1];
            float2 v0 = make_float2(c[mi][nj][0] + b0, c[mi][nj][1] + b1);
            float2 v1 = make_float2(c[mi][nj][2] + b0, c[mi][nj][3] + b1);
            *(float2*)&g_gates[(size_t)r * GG + cn] = v0;
            *(float2*)&g_gates[(size_t)(r + 8) * GG + cn] = v1;
        }
    }
}

extern __shared__ float dsm[];

// ---------------------------------------------------------------------------
// Persistent recurrence kernel v8.1: NO staging — A-operands (h, rh) loaded
// directly from gmem exchange buffers; B (weights) in smem via ldmatrix.
// 128 CTAs x 128 threads (4 warps: mi = wid&1, kh = wid>>1, k split 2-way).
// CTA x<64 owns z cols [16x,16x+16); x>=64 owns r cols [16(x-64),+16).
// All CTAs own a cols [8x, 8x+8).
// smem: sWh (24 rows) + sWl (24 rows) + 8 PAD rows (phase2 ldmatrix.x4
// overspill: lanes 16-31 address rows 24..31 of the WL array; fragments
// unused, addresses must be in-bounds) + red buffer.
// ---------------------------------------------------------------------------
#define HSTR 2064
#define OFF_WH 0
#define OFF_WL 49536                    // 24*HSTR
#define OFF_RED (OFF_WL + 32 * HSTR)    // 115584 (incl. 8-row overspill pad)
#define SMEM_GRU3 (OFF_RED + 6144)      // 121728

__global__ __launch_bounds__(GTHR, 1) void gru_persistent(
    const float* __restrict__ w_h, const float* __restrict__ h0,
    float* out0, float* __restrict__ out1)
{
    char* sm = (char*)dsm;
    float4* sred = (float4*)(sm + OFF_RED);   // [ (mi*6+q)*32 + lane ]

    const int x = blockIdx.x;
    const int tid = threadIdx.x;
    const int lane = tid & 31;
    const int wid = tid >> 5;
    const int mi = wid & 1;
    const int kh = wid >> 1;
    const int leaf = x & 15;

    // ---- one-time weight preload + split into sWh/sWl ----
    for (int i = tid; i < 24 * 1024; i += GTHR) {
        int c = i >> 10, k = i & 1023;
        int gcol = (c < 16) ? (x * 16 + c) : (2048 + x * 8 + (c - 16));
        float v = w_h[(size_t)k * GG + gcol];
        __nv_bfloat16 h = __float2bfloat16(v);
        __nv_bfloat16 l = __float2bfloat16(v - __bfloat162float(h));
        *(__nv_bfloat16*)(sm + OFF_WH + c * HSTR + 2 * k) = h;
        *(__nv_bfloat16*)(sm + OFF_WL + c * HSTR + 2 * k) = l;
    }
    __syncthreads();

    // B ldmatrix bases (validated pattern), offset by k-half
    uint32_t aBh = smem_u32(sm + OFF_WH
        + ((lane & 7) + ((lane >> 4) & 1) * 8) * HSTR
        + ((lane >> 3) & 1) * 16) + kh * 1024;
    uint32_t aBl = aBh + (OFF_WL - OFF_WH);
    uint32_t aB2h = aBh + 16 * HSTR;
    uint32_t aB2l = aBl + 16 * HSTR;

    const int frow = lane >> 2;        // 0..7
    const int fcol = (lane & 3) * 2;
    const int kpb = lane & 3;          // A kpair lane offset
    const int r0 = mi * 16 + frow;     // A-fragment rows (batches)
    const int r1 = r0 + 8;
    const int ksb = kh * 32;           // this warp's k16-range start

    // phase2 A pointers (rh — no reset logic)
    const uint32_t* pR0h = g_rhh + r0 * 512;
    const uint32_t* pR1h = g_rhh + r1 * 512;
    const uint32_t* pR0l = g_rhl + r0 * 512;
    const uint32_t* pR1l = g_rhl + r1 * 512;

    for (int t = 0; t < TT; t++) {
        unsigned rm = g_rmask[t];

        // phase1 A pointers (reset-aware per row)
        const uint32_t* pH0h = ((rm >> r0) & 1u) ? g_h0h : g_hh + r0 * 512;
        const uint32_t* pH0l = ((rm >> r0) & 1u) ? g_h0l : g_hl + r0 * 512;
        const uint32_t* pH1h = ((rm >> r1) & 1u) ? g_h0h : g_hh + r1 * 512;
        const uint32_t* pH1l = ((rm >> r1) & 1u) ? g_h0l : g_hl + r1 * 512;

        // ---- prefetch gates for this step (kh==0 warps finalize) ----
        float2 gx1[2][2], gx2[2];
        if (kh == 0) {
            int b0 = mi * 16 + frow;
#pragma unroll
            for (int hh = 0; hh < 2; hh++) {
                size_t grow = ((size_t)(b0 + hh * 8) * TT + t) * GG;
#pragma unroll
                for (int nj = 0; nj < 2; nj++)
                    gx1[nj][hh] = *(const float2*)&g_gates[grow + x * 16 + nj * 8 + fcol];
                gx2[hh] = *(const float2*)&g_gates[grow + 2048 + x * 8 + fcol];
            }
        }

        // ---- wait for barrier 2 of previous step (h(t-1) ready) ----
        if (t > 0) {
            unsigned n = 2u * t;
            if (tid == 0) {
                while (*(volatile unsigned*)&g_release < n) __nanosleep(32);
                __threadfence();
            }
            __syncthreads();
        }

        // ================= phase 1: zr preactivations =================
        float acc[6][4];
#pragma unroll
        for (int q = 0; q < 6; q++)
#pragma unroll
            for (int e = 0; e < 4; e++) acc[q][e] = 0.0f;
        {
            uint32_t Ah[4][4], Al[4][4], Bh[2][4], Bl[2][4];
#pragma unroll
            for (int d = 0; d < 4; d++) {
                int kp = (ksb + d) * 8 + kpb;
                loadA4(Ah[d], pH0h, pH1h, kp);
                loadA4(Al[d], pH0l, pH1l, kp);
            }
            LDSM_X4(Bh[0], aBh);
            LDSM_X4(Bl[0], aBl);
#pragma unroll
            for (int j = 0; j < 32; j++) {
                const int d = j & 3;
                const int cb = j & 1;
                if (j < 31) {
                    LDSM_X4(Bh[cb ^ 1], aBh + (j + 1) * 32);
                    LDSM_X4(Bl[cb ^ 1], aBl + (j + 1) * 32);
                }
                MMA_BF16(acc[0], Ah[d], Bh[cb][0], Bh[cb][1]);
                MMA_BF16(acc[1], Ah[d], Bh[cb][2], Bh[cb][3]);
                MMA_BF16(acc[2], Ah[d], Bl[cb][0], Bl[cb][1]);
                MMA_BF16(acc[3], Ah[d], Bl[cb][2], Bl[cb][3]);
                MMA_BF16(acc[4], Al[d], Bh[cb][0], Bh[cb][1]);
                MMA_BF16(acc[5], Al[d], Bh[cb][2], Bh[cb][3]);
                if (j < 28) {
                    int kp = (ksb + j + 4) * 8 + kpb;
                    loadA4(Ah[d], pH0h, pH1h, kp);
                    loadA4(Al[d], pH0l, pH1l, kp);
                }
            }
        }
        // cross-warp k reduction
        if (kh == 1) {
#pragma unroll
            for (int q = 0; q < 6; q++)
                sred[(mi * 6 + q) * 32 + lane] =
                    make_float4(acc[q][0], acc[q][1], acc[q][2], acc[q][3]);
        }
        __syncthreads();
        if (kh == 0) {
#pragma unroll
            for (int q = 0; q < 6; q++) {
                float4 p = sred[(mi * 6 + q) * 32 + lane];
                acc[q][0] += p.x; acc[q][1] += p.y;
                acc[q][2] += p.z; acc[q][3] += p.w;
            }
            int b0 = mi * 16 + frow;
#pragma unroll
            for (int nj = 0; nj < 2; nj++) {
                float c0 = acc[nj][0] + acc[nj + 2][0] + acc[nj + 4][0];
                float c1 = acc[nj][1] + acc[nj + 2][1] + acc[nj + 4][1];
                float c2 = acc[nj][2] + acc[nj + 2][2] + acc[nj + 4][2];
                float c3 = acc[nj][3] + acc[nj + 2][3] + acc[nj + 4][3];
                float2 s0, s1;
                s0.x = 1.0f / (1.0f + __expf(-(gx1[nj][0].x + c0)));
                s0.y = 1.0f / (1.0f + __expf(-(gx1[nj][0].y + c1)));
                s1.x = 1.0f / (1.0f + __expf(-(gx1[nj][1].x + c2)));
                s1.y = 1.0f / (1.0f + __expf(-(gx1[nj][1].y + c3)));
                if (x < 64) {
                    int col = x * 16 + nj * 8 + fcol;
                    *(float2*)&g_zr[b0 * 2048 + col] = s0;
                    *(float2*)&g_zr[(b0 + 8) * 2048 + col] = s1;
                } else {
                    int col = (x - 64) * 16 + nj * 8 + fcol;
                    int kp = col >> 1;
#pragma unroll
                    for (int hh = 0; hh < 2; hh++) {
                        int b = b0 + hh * 8;
                        float2 rr = hh ? s1 : s0;
                        bool rs = (rm >> b) & 1u;
                        uint32_t hhi = rs ? __ldg(&g_h0h[kp])
                                          : __ldcg(&g_hh[b * 512 + kp]);
                        uint32_t hlo = rs ? __ldg(&g_h0l[kp])
                                          : __ldcg(&g_hl[b * 512 + kp]);
                        float2 hf = join2(hhi, hlo);
                        float2 rh = make_float2(rr.x * hf.x, rr.y * hf.y);
                        uint32_t ohi, olo;
                        split2(rh, ohi, olo);
                        g_rhh[b * 512 + kp] = ohi;
                        g_rhl[b * 512 + kp] = olo;
                    }
                }
            }
        }

        // ---- barrier 1 (z / rh visible to all CTAs) ----
        unsigned n1 = 2u * t + 1u;
        __syncthreads();
        if (tid == 0) {
            __threadfence();
            unsigned o = atomicAdd(&g_leaf[leaf], 1u);
            if (o == n1 * 8u - 1u) {
                unsigned o2 = atomicAdd(&g_root, 1u);
                if (o2 == n1 * 16u - 1u) atomicExch(&g_release, n1);
            }
            while (*(volatile unsigned*)&g_release < n1) __nanosleep(32);
            __threadfence();
        }
        __syncthreads();

        // ================= phase 2: a = tanh(gx + rh @ Wa) =================
        float ac2[3][4];
#pragma unroll
        for (int q = 0; q < 3; q++)
#pragma unroll
            for (int e = 0; e < 4; e++) ac2[q][e] = 0.0f;
        {
            uint32_t Ah[4][4], Al[4][4], Bh[2][4], Bl[2][4];
#pragma unroll
            for (int d = 0; d < 4; d++) {
                int kp = (ksb + d) * 8 + kpb;
                loadA4(Ah[d], pR0h, pR1h, kp);
                loadA4(Al[d], pR0l, pR1l, kp);
            }
            LDSM_X4(Bh[0], aB2h);
            LDSM_X4(Bl[0], aB2l);
#pragma unroll
            for (int j = 0; j < 32; j++) {
                const int d = j & 3;
                const int cb = j & 1;
                if (j < 31) {
                    LDSM_X4(Bh[cb ^ 1], aB2h + (j + 1) * 32);
                    LDSM_X4(Bl[cb ^ 1], aB2l + (j + 1) * 32);
                }
                MMA_BF16(ac2[0], Ah[d], Bh[cb][0], Bh[cb][1]);
                MMA_BF16(ac2[1], Ah[d], Bl[cb][0], Bl[cb][1]);
                MMA_BF16(ac2[2], Al[d], Bh[cb][0], Bh[cb][1]);
                if (j < 28) {
                    int kp = (ksb + j + 4) * 8 + kpb;
                    loadA4(Ah[d], pR0h, pR1h, kp);
                    loadA4(Al[d], pR0l, pR1l, kp);
                }
            }
        }
        if (kh == 1) {
#pragma unroll
            for (int q = 0; q < 3; q++)
                sred[(mi * 3 + q) * 32 + lane] =
                    make_float4(ac2[q][0], ac2[q][1], ac2[q][2], ac2[q][3]);
        }
        __syncthreads();
        if (kh == 0) {
            float cc[4];
#pragma unroll
            for (int e = 0; e < 4; e++) cc[e] = ac2[0][e] + ac2[1][e] + ac2[2][e];
#pragma unroll
            for (int q = 0; q < 3; q++) {
                float4 p = sred[(mi * 3 + q) * 32 + lane];
                cc[0] += p.x; cc[1] += p.y; cc[2] += p.z; cc[3] += p.w;
            }

            int col = x * 8 + fcol;
            int kp = col >> 1;
#pragma unroll
            for (int hh = 0; hh < 2; hh++) {
                int b = mi * 16 + frow + hh * 8;
                float a0 = tanhf(gx2[hh].x + cc[hh * 2 + 0]);
                float a1 = tanhf(gx2[hh].y + cc[hh * 2 + 1]);
                bool rs = (rm >> b) & 1u;
                uint32_t hhi = rs ? __ldg(&g_h0h[kp])
                                  : __ldcg(&g_hh[b * 512 + kp]);
                uint32_t hlo = rs ? __ldg(&g_h0l[kp])
                                  : __ldcg(&g_hl[b * 512 + kp]);
                float2 hw = join2(hhi, hlo);
                float2 z = __ldcg((const float2*)&g_zr[b * 2048 + col]);
                float2 hn;
                hn.x = (1.0f - z.x) * hw.x + z.x * a0;
                hn.y = (1.0f - z.y) * hw.y + z.y * a1;
                size_t o = ((size_t)b * TT + t) * HH + col;
                *(float2*)&out0[o] = hn;
                *(float2*)&out1[o] = hn;
                uint32_t nhi, nlo;
                split2(hn, nhi, nlo);
                g_hh[b * 512 + kp] = nhi;
                g_hl[b * 512 + kp] = nlo;
            }
        }

        // ---- barrier 2 arrive (h(t) ready); wait at next loop top ----
        unsigned n2 = 2u * t + 2u;
        __syncthreads();
        if (tid == 0) {
            __threadfence();
            unsigned o = atomicAdd(&g_leaf[leaf], 1u);
            if (o == n2 * 8u - 1u) {
                unsigned o2 = atomicAdd(&g_root, 1u);
                if (o2 == n2 * 16u - 1u) atomicExch(&g_release, n2);
            }
        }
    }
}

// ---------------------------------------------------------------------------
// Epilogue: runs BEFORE gru each replay — zero barriers, write outh, split h0.
// ---------------------------------------------------------------------------
__global__ void epilogue(const float* __restrict__ h0, float* __restrict__ dst)
{
    int i = blockIdx.x * blockDim.x + threadIdx.x;
    if (i < HH) dst[i] = h0[i];
    if (i < 512) {
        float2 v = *(const float2*)&h0[i * 2];
        uint32_t hi, lo;
        split2(v, hi, lo);
        g_h0h[i] = hi;
        g_h0l[i] = lo;
    }
    if (i < 16) g_leaf[i] = 0;
    if (i == 16) g_root = 0;
    if (i == 17) g_release = 0;
}

// ---------------------------------------------------------------------------
extern "C" void kernel_launch(void* const* d_in, const int* in_sizes, int n_in,
                              void* d_out, int out_size)
{
    const float* x = (const float*)d_in[0];
    const unsigned char* reset_raw = (const unsigned char*)d_in[1];
    const float* w_i = (const float*)d_in[2];
    const float* w_h = (const float*)d_in[3];
    const float* b = (const float*)d_in[4];
    const float* h0 = (const float*)d_in[5];

    float* out0 = (float*)d_out;
    float* out1 = out0 + (size_t)NB * TT * HH;
    float* outh = out1 + (size_t)NB * TT * HH;

    cudaFuncSetAttribute(gru_persistent,
                         cudaFuncAttributeMaxDynamicSharedMemorySize, SMEM_GRU3);

    // 0) reset masks + split-precision conversion
    prep_reset<<<1, 512>>>(reset_raw);
    conv_x<<<(NB * TT * DD + 255) / 256, 256>>>(x);
    conv_w<<<(DD * GG + 255) / 256, 256>>>(w_i);

    // 1) gates = x @ w_i + b via mma.sync bf16 (split precision, f32 accum)
    {
        dim3 grid(GG / 128, (NB * TT) / 128);
        mma_gates<<<grid, 256>>>(b);
    }

    // 2) barrier state reset + third output + h0 bf16 split
    epilogue<<<1, 1024>>>(h0, outh);

    // 3) full recurrence in ONE persistent kernel (no staging, direct-gmem A)
    gru_persistent<<<NCTA, GTHR, SMEM_GRU3>>>(w_h, h0, out0, out1);
}

// round 15
// speedup vs baseline: 1.8981x; 1.8981x over previous
#include <cuda_runtime.h>
#include <cuda_bf16.h>
#include <cstdint>

// Problem constants
#define NB 32      // batch
#define TT 512     // time steps
#define DD 512     // input dim
#define HH 1024    // hidden dim
#define GG 3072    // 3*H

#define NCTA 128   // persistent grid
#define NTHR 512

// Scratch (module-load allocated; no runtime alloc)
__device__ float g_gates[(size_t)NB * TT * GG];  // 16384 x 3072
__device__ float g_zr[NB * 2 * HH];              // z region used (cols 0..1023)
__device__ unsigned g_rmask[TT];                 // per-step reset bitmasks

// bf16 hi/lo exchange buffers (uint32 = packed bf16 col-pair)
__device__ uint32_t g_hh[NB * 512];   // h(t) hi
__device__ uint32_t g_hl[NB * 512];   // h(t) lo
__device__ uint32_t g_rhh[NB * 512];  // rh hi
__device__ uint32_t g_rhl[NB * 512];  // rh lo
__device__ uint32_t g_h0h[512];       // h0 hi
__device__ uint32_t g_h0l[512];       // h0 lo

// split-precision bf16 operands for the gates GEMM
__device__ __nv_bfloat16 g_xhi[(size_t)NB * TT * DD];
__device__ __nv_bfloat16 g_xlo[(size_t)NB * TT * DD];
__device__ __nv_bfloat16 g_whi[(size_t)GG * DD];   // transposed [n][k]
__device__ __nv_bfloat16 g_wlo[(size_t)GG * DD];

// Hierarchical barrier state (zeroed by epilogue BEFORE gru each replay)
__device__ unsigned g_leaf[16];
__device__ unsigned g_root;
__device__ unsigned g_release;

__device__ __forceinline__ uint32_t smem_u32(const void* p)
{
    uint32_t a;
    asm("{ .reg .u64 t; cvta.to.shared.u64 t, %1; cvt.u32.u64 %0, t; }"
        : "=r"(a) : "l"(p));
    return a;
}

// ldmatrix x4 / x2 (8x8 b16 tiles)
#define LDSM_X4(r, a) \
    asm volatile("ldmatrix.sync.aligned.m8n8.x4.shared.b16 {%0,%1,%2,%3}, [%4];" \
        : "=r"((r)[0]), "=r"((r)[1]), "=r"((r)[2]), "=r"((r)[3]) : "r"(a))
#define LDSM_X2(r, a) \
    asm volatile("ldmatrix.sync.aligned.m8n8.x2.shared.b16 {%0,%1}, [%2];" \
        : "=r"((r)[0]), "=r"((r)[1]) : "r"(a))

// bf16 m16n8k16 mma, f32 accum
#define MMA_BF16(c, a, b0, b1) \
    asm volatile("mma.sync.aligned.m16n8k16.row.col.f32.bf16.bf16.f32 " \
        "{%0,%1,%2,%3}, {%4,%5,%6,%7}, {%8,%9}, {%0,%1,%2,%3};" \
        : "+f"((c)[0]), "+f"((c)[1]), "+f"((c)[2]), "+f"((c)[3]) \
        : "r"((a)[0]), "r"((a)[1]), "r"((a)[2]), "r"((a)[3]), "r"(b0), "r"(b1))

// split float2 -> packed bf16 hi/lo uint32s
__device__ __forceinline__ void split2(float2 v, uint32_t& hi, uint32_t& lo)
{
    __nv_bfloat162 h2 = __floats2bfloat162_rn(v.x, v.y);
    float2 hf = __bfloat1622float2(h2);
    __nv_bfloat162 l2 = __floats2bfloat162_rn(v.x - hf.x, v.y - hf.y);
    hi = *(uint32_t*)&h2;
    lo = *(uint32_t*)&l2;
}

__device__ __forceinline__ float2 join2(uint32_t hi, uint32_t lo)
{
    float2 h = __bfloat1622float2(*(__nv_bfloat162*)&hi);
    float2 l = __bfloat1622float2(*(__nv_bfloat162*)&lo);
    return make_float2(h.x + l.x, h.y + l.y);
}

// ---------------------------------------------------------------------------
// Prep: detect reset dtype (bool8 vs int32), build per-step bitmasks.
// ---------------------------------------------------------------------------
__global__ void prep_reset(const unsigned char* __restrict__ raw)
{
    __shared__ int s_bool8;
    int tid = threadIdx.x;
    if (tid == 0) s_bool8 = 0;
    __syncthreads();
    for (int i = tid; i < 4096; i += blockDim.x)
        if ((i & 3) != 0 && raw[i] != 0) s_bool8 = 1;
    __syncthreads();
    bool b8 = (s_bool8 != 0);
    const int* r32 = (const int*)raw;
    for (int t = tid; t < TT; t += blockDim.x) {
        unsigned m = 0;
        for (int b = 0; b < NB; b++) {
            bool rv = b8 ? (raw[b * TT + t] != 0) : (r32[b * TT + t] != 0);
            if (rv) m |= (1u << b);
        }
        if (t == 0) m = 0xFFFFFFFFu;
        g_rmask[t] = m;
    }
}

// ---------------------------------------------------------------------------
// Split-precision conversion kernels (gates GEMM inputs)
// ---------------------------------------------------------------------------
__global__ void conv_x(const float* __restrict__ x)
{
    int i = blockIdx.x * blockDim.x + threadIdx.x;
    if (i < NB * TT * DD) {
        float v = x[i];
        __nv_bfloat16 h = __float2bfloat16(v);
        g_xhi[i] = h;
        g_xlo[i] = __float2bfloat16(v - __bfloat162float(h));
    }
}

__global__ void conv_w(const float* __restrict__ w)
{
    int i = blockIdx.x * blockDim.x + threadIdx.x;
    if (i < DD * GG) {
        int k = i / GG;
        int n = i % GG;
        float v = w[i];
        __nv_bfloat16 h = __float2bfloat16(v);
        g_whi[(size_t)n * DD + k] = h;
        g_wlo[(size_t)n * DD + k] = __float2bfloat16(v - __bfloat162float(h));
    }
}

// ---------------------------------------------------------------------------
// Tensor-core gates GEMM (unchanged from R10 — validated, 435us)
// ---------------------------------------------------------------------------
#define ASTR 40

__global__ __launch_bounds__(256) void mma_gates(const float* __restrict__ bias)
{
    __shared__ __nv_bfloat16 sAh[128][ASTR];
    __shared__ __nv_bfloat16 sAl[128][ASTR];
    __shared__ __nv_bfloat16 sBh[128][ASTR];
    __shared__ __nv_bfloat16 sBl[128][ASTR];

    const int tid = threadIdx.x;
    const int lane = tid & 31;
    const int wid = tid >> 5;
    const int wm = wid & 1;
    const int wn = wid >> 1;
    const int bn = blockIdx.x * 128;
    const int bm = blockIdx.y * 128;

    float c[4][4][4];
#pragma unroll
    for (int i = 0; i < 4; i++)
#pragma unroll
        for (int j = 0; j < 4; j++)
#pragma unroll
            for (int q = 0; q < 4; q++) c[i][j][q] = 0.0f;

    const int a_row = wm * 64 + (lane & 7) + ((lane >> 3) & 1) * 8;
    const int a_col = ((lane >> 4) & 1) * 8;
    const int b_row = wn * 32 + (lane & 7) + ((lane >> 4) & 1) * 8;
    const int b_col = ((lane >> 3) & 1) * 8;

    for (int kc = 0; kc < 16; kc++) {
        for (int i = tid; i < 512; i += 256) {
            int row = i >> 2;
            int c8 = (i & 3) * 8;
            size_t ga = (size_t)(bm + row) * DD + kc * 32 + c8;
            size_t gb = (size_t)(bn + row) * DD + kc * 32 + c8;
            *(uint4*)&sAh[row][c8] = *(const uint4*)&g_xhi[ga];
            *(uint4*)&sAl[row][c8] = *(const uint4*)&g_xlo[ga];
            *(uint4*)&sBh[row][c8] = *(const uint4*)&g_whi[gb];
            *(uint4*)&sBl[row][c8] = *(const uint4*)&g_wlo[gb];
        }
        __syncthreads();

#pragma unroll
        for (int ks = 0; ks < 2; ks++) {
            const int k0 = ks * 16;
            uint32_t ah[4][4], al[4][4], bh[2][4], bl[2][4];
#pragma unroll
            for (int mi = 0; mi < 4; mi++) {
                uint32_t adr = smem_u32(&sAh[a_row + mi * 16][k0 + a_col]);
                LDSM_X4(ah[mi], adr);
                adr = smem_u32(&sAl[a_row + mi * 16][k0 + a_col]);
                LDSM_X4(al[mi], adr);
            }
#pragma unroll
            for (int j = 0; j < 2; j++) {
                uint32_t adr = smem_u32(&sBh[b_row + j * 16][k0 + b_col]);
                LDSM_X4(bh[j], adr);
                adr = smem_u32(&sBl[b_row + j * 16][k0 + b_col]);
                LDSM_X4(bl[j], adr);
            }
#pragma unroll
            for (int mi = 0; mi < 4; mi++) {
#pragma unroll
                for (int nj = 0; nj < 4; nj++) {
                    int j = nj >> 1, p = (nj & 1) * 2;
                    MMA_BF16(c[mi][nj], ah[mi], bh[j][p], bh[j][p + 1]);
                    MMA_BF16(c[mi][nj], ah[mi], bl[j][p], bl[j][p + 1]);
                    MMA_BF16(c[mi][nj], al[mi], bh[j][p], bh[j][p + 1]);
                }
            }
        }
        __syncthreads();
    }

#pragma unroll
    for (int mi = 0; mi < 4; mi++) {
#pragma unroll
        for (int nj = 0; nj < 4; nj++) {
            int r = bm + wm * 64 + mi * 16 + (lane >> 2);
            int cn = bn + wn * 32 + nj * 8 + (lane & 3) * 2;
            float b0 = bias[cn], b1 = bias[cn + 1];
            float2 v0 = make_float2(c[mi][nj][0] + b0, c[mi][nj][1] + b1);
            float2 v1 = make_float2(c[mi][nj][2] + b0, c[mi][nj][3] + b1);
            *(float2*)&g_gates[(size_t)r * GG + cn] = v0;
            *(float2*)&g_gates[(size_t)(r + 8) * GG + cn] = v1;
        }
    }
}

extern __shared__ float dsm[];

// ---------------------------------------------------------------------------
// Persistent recurrence kernel v9 = R12(v7) base + wider MMA parallelism:
//   phase1: 4 warps (mi x nh n-split), no reduction, ldmatrix.x2 B
//   phase2: 4 warps (mi x kq k-split), 1KB pre-reduced smem reduction
// smem: sWh/sWl (24 x 1032 bf16) + sHh/sHl (32 x 1032 bf16) + red 1KB
// ---------------------------------------------------------------------------
#define HSTR 2064
#define OFF_WH 0
#define OFF_WL 49536
#define OFF_HH 99072
#define OFF_HL 165120
#define OFF_RED 231168
#define SMEM_GRU2 (OFF_RED + 1024)   // 232192 <= 232448 cap

__global__ __launch_bounds__(NTHR, 1) void gru_persistent(
    const float* __restrict__ w_h, const float* __restrict__ h0,
    float* out0, float* __restrict__ out1)
{
    char* sm = (char*)dsm;
    float4* sred = (float4*)(sm + OFF_RED);   // [mi*32 + lane]

    const int x = blockIdx.x;
    const int tid = threadIdx.x;
    const int lane = tid & 31;
    const int wid = tid >> 5;
    const int leaf = x & 15;

    // ---- one-time weight preload + split into sWh/sWl ----
    for (int i = tid; i < 24 * 1024; i += NTHR) {
        int c = i >> 10, k = i & 1023;
        int gcol = (c < 16) ? (x * 16 + c) : (2048 + x * 8 + (c - 16));
        float v = w_h[(size_t)k * GG + gcol];
        __nv_bfloat16 h = __float2bfloat16(v);
        __nv_bfloat16 l = __float2bfloat16(v - __bfloat162float(h));
        *(__nv_bfloat16*)(sm + OFF_WH + c * HSTR + 2 * k) = h;
        *(__nv_bfloat16*)(sm + OFF_WL + c * HSTR + 2 * k) = l;
    }
    __syncthreads();

    // warp roles: phase1 (mi, nh); phase2 (mi, kq) — same bit for nh/kq
    const int mi = wid & 1;
    const int sp = (wid >> 1) & 1;     // nh in phase1, kq in phase2

    // A ldmatrix base (R12-validated fragment pattern)
    uint32_t aAh = smem_u32(sm + OFF_HH
        + (mi * 16 + (lane & 7) + ((lane >> 3) & 1) * 8) * HSTR
        + ((lane >> 4) & 1) * 16);
    uint32_t aAl = aAh + (OFF_HL - OFF_HH);

    // phase1 B (x2): rows = local zr cols nh*8..+8
    uint32_t aB1h = smem_u32(sm + OFF_WH
        + (sp * 8 + (lane & 7)) * HSTR + ((lane >> 3) & 1) * 16);
    uint32_t aB1l = aB1h + (OFF_WL - OFF_WH);

    // phase2 B (x2): rows = W rows 16..23 (a-cols), k offset by kq half
    uint32_t aB2h = smem_u32(sm + OFF_WH
        + (16 + (lane & 7)) * HSTR + ((lane >> 3) & 1) * 16) + sp * 1024;
    uint32_t aB2l = aB2h + (OFF_WL - OFF_WH);
    uint32_t aA2h = aAh + sp * 1024;
    uint32_t aA2l = aAl + sp * 1024;

    const int frow = lane >> 2;
    const int fcol = (lane & 3) * 2;

    const uint2* hh2 = (const uint2*)g_hh;
    const uint2* hl2 = (const uint2*)g_hl;
    const uint2* rhh2 = (const uint2*)g_rhh;
    const uint2* rhl2 = (const uint2*)g_rhl;
    const uint2* h0h2 = (const uint2*)g_h0h;
    const uint2* h0l2 = (const uint2*)g_h0l;

    for (int t = 0; t < TT; t++) {
        unsigned rm = g_rmask[t];

        // ---- prefetch gates for this step ----
        float2 gx1[2], gx2[2];
        if (wid < 4) {
            int b0 = mi * 16 + frow;
#pragma unroll
            for (int hh = 0; hh < 2; hh++) {
                size_t grow = ((size_t)(b0 + hh * 8) * TT + t) * GG;
                gx1[hh] = *(const float2*)&g_gates[grow + x * 16 + sp * 8 + fcol];
                if (wid < 2)
                    gx2[hh] = *(const float2*)&g_gates[grow + 2048 + x * 8 + fcol];
            }
        }

        // ---- wait for barrier 2 of previous step (h(t-1) bf16 ready) ----
        if (t > 0) {
            unsigned n = 2u * t;
            if (tid == 0) {
                while (*(volatile unsigned*)&g_release < n) __nanosleep(32);
                __threadfence();
            }
            __syncthreads();
        }

        // ---- stage h_eff bf16 (pure copy) ----
        for (int i = tid; i < 8192; i += NTHR) {
            int b = i >> 8, k4 = i & 255;
            uint2 hi, lo;
            if ((rm >> b) & 1u) {
                hi = __ldg(&h0h2[k4]);
                lo = __ldg(&h0l2[k4]);
            } else {
                hi = __ldcg(&hh2[b * 256 + k4]);
                lo = __ldcg(&hl2[b * 256 + k4]);
            }
            *(uint2*)(sm + OFF_HH + b * HSTR + k4 * 8) = hi;
            *(uint2*)(sm + OFF_HL + b * HSTR + k4 * 8) = lo;
        }
        __syncthreads();

        // ---- phase1 MMA: 4 warps (mi x nh), full k, no reduction ----
        if (wid < 4) {
            float acc[3][4];
#pragma unroll
            for (int q = 0; q < 3; q++)
#pragma unroll
                for (int e = 0; e < 4; e++) acc[q][e] = 0.0f;
            uint32_t pAh = aAh, pAl = aAl, pBh = aB1h, pBl = aB1l;
#pragma unroll 4
            for (int ks = 0; ks < 64; ks++) {
                uint32_t Ah[4], Al[4], Bh[2], Bl[2];
                LDSM_X4(Ah, pAh); LDSM_X4(Al, pAl);
                LDSM_X2(Bh, pBh); LDSM_X2(Bl, pBl);
                MMA_BF16(acc[0], Ah, Bh[0], Bh[1]);
                MMA_BF16(acc[1], Ah, Bl[0], Bl[1]);
                MMA_BF16(acc[2], Al, Bh[0], Bh[1]);
                pAh += 32; pAl += 32; pBh += 32; pBl += 32;
            }
            float c0 = acc[0][0] + acc[1][0] + acc[2][0];
            float c1 = acc[0][1] + acc[1][1] + acc[2][1];
            float c2 = acc[0][2] + acc[1][2] + acc[2][2];
            float c3 = acc[0][3] + acc[1][3] + acc[2][3];
            float2 s0, s1;
            s0.x = 1.0f / (1.0f + __expf(-(gx1[0].x + c0)));
            s0.y = 1.0f / (1.0f + __expf(-(gx1[0].y + c1)));
            s1.x = 1.0f / (1.0f + __expf(-(gx1[1].x + c2)));
            s1.y = 1.0f / (1.0f + __expf(-(gx1[1].y + c3)));
            int b0 = mi * 16 + frow;
            if (x < 64) {
                int col = x * 16 + sp * 8 + fcol;
                *(float2*)&g_zr[b0 * 2048 + col] = s0;
                *(float2*)&g_zr[(b0 + 8) * 2048 + col] = s1;
            } else {
                int col = (x - 64) * 16 + sp * 8 + fcol;
                int kp = col >> 1;
#pragma unroll
                for (int hh = 0; hh < 2; hh++) {
                    int b = b0 + hh * 8;
                    float2 rr = hh ? s1 : s0;
                    uint32_t hhi = *(uint32_t*)(sm + OFF_HH + b * HSTR + col * 2);
                    uint32_t hlo = *(uint32_t*)(sm + OFF_HL + b * HSTR + col * 2);
                    float2 hf = join2(hhi, hlo);
                    float2 rh = make_float2(rr.x * hf.x, rr.y * hf.y);
                    uint32_t ohi, olo;
                    split2(rh, ohi, olo);
                    g_rhh[b * 512 + kp] = ohi;
                    g_rhl[b * 512 + kp] = olo;
                }
            }
        }

        // ---- barrier 1 (z / rh visible to all CTAs) ----
        unsigned n1 = 2u * t + 1u;
        __syncthreads();
        if (tid == 0) {
            __threadfence();
            unsigned o = atomicAdd(&g_leaf[leaf], 1u);
            if (o == n1 * 8u - 1u) {
                unsigned o2 = atomicAdd(&g_root, 1u);
                if (o2 == n1 * 16u - 1u) atomicExch(&g_release, n1);
            }
            while (*(volatile unsigned*)&g_release < n1) __nanosleep(32);
            __threadfence();
        }
        __syncthreads();

        // ---- stash h(t-1) + z at own a-cols (before smem overwrite) ----
        float2 hw[2], zz[2];
        if (wid < 2) {
            int col = x * 8 + fcol;
#pragma unroll
            for (int hh = 0; hh < 2; hh++) {
                int b = mi * 16 + frow + hh * 8;
                uint32_t hhi = *(uint32_t*)(sm + OFF_HH + b * HSTR + col * 2);
                uint32_t hlo = *(uint32_t*)(sm + OFF_HL + b * HSTR + col * 2);
                hw[hh] = join2(hhi, hlo);
                zz[hh] = __ldcg((const float2*)&g_zr[b * 2048 + col]);
            }
        }
        __syncthreads();

        // ---- restage rh bf16 (pure copy) ----
        for (int i = tid; i < 8192; i += NTHR) {
            int b = i >> 8, k4 = i & 255;
            uint2 hi = __ldcg(&rhh2[b * 256 + k4]);
            uint2 lo = __ldcg(&rhl2[b * 256 + k4]);
            *(uint2*)(sm + OFF_HH + b * HSTR + k4 * 8) = hi;
            *(uint2*)(sm + OFF_HL + b * HSTR + k4 * 8) = lo;
        }
        __syncthreads();

        // ---- phase2 MMA: 4 warps (mi x kq), half k each ----
        float cc[4] = {0.f, 0.f, 0.f, 0.f};
        if (wid < 4) {
            float ac2[3][4];
#pragma unroll
            for (int q = 0; q < 3; q++)
#pragma unroll
                for (int e = 0; e < 4; e++) ac2[q][e] = 0.0f;
            uint32_t pAh = aA2h, pAl = aA2l, pBh = aB2h, pBl = aB2l;
#pragma unroll 4
            for (int ks = 0; ks < 32; ks++) {
                uint32_t Ah[4], Al[4], Bh[2], Bl[2];
                LDSM_X4(Ah, pAh); LDSM_X4(Al, pAl);
                LDSM_X2(Bh, pBh); LDSM_X2(Bl, pBl);
                MMA_BF16(ac2[0], Ah, Bh[0], Bh[1]);
                MMA_BF16(ac2[1], Ah, Bl[0], Bl[1]);
                MMA_BF16(ac2[2], Al, Bh[0], Bh[1]);
                pAh += 32; pAl += 32; pBh += 32; pBl += 32;
            }
#pragma unroll
            for (int e = 0; e < 4; e++)
                cc[e] = ac2[0][e] + ac2[1][e] + ac2[2][e];
        }
        // cross-warp k reduction: kq==1 warps (wid 2,3) publish, kq==0 fold
        if (wid >= 2 && wid < 4)
            sred[mi * 32 + lane] = make_float4(cc[0], cc[1], cc[2], cc[3]);
        __syncthreads();
        if (wid < 2) {
            float4 p = sred[mi * 32 + lane];
            cc[0] += p.x; cc[1] += p.y; cc[2] += p.z; cc[3] += p.w;

            int col = x * 8 + fcol;
            int kp = col >> 1;
#pragma unroll
            for (int hh = 0; hh < 2; hh++) {
                int b = mi * 16 + frow + hh * 8;
                float a0 = tanhf(gx2[hh].x + cc[hh * 2 + 0]);
                float a1 = tanhf(gx2[hh].y + cc[hh * 2 + 1]);
                float2 hn;
                hn.x = (1.0f - zz[hh].x) * hw[hh].x + zz[hh].x * a0;
                hn.y = (1.0f - zz[hh].y) * hw[hh].y + zz[hh].y * a1;
                size_t o = ((size_t)b * TT + t) * HH + col;
                *(float2*)&out0[o] = hn;
                *(float2*)&out1[o] = hn;
                uint32_t nhi, nlo;
                split2(hn, nhi, nlo);
                g_hh[b * 512 + kp] = nhi;
                g_hl[b * 512 + kp] = nlo;
            }
        }

        // ---- barrier 2 arrive (h(t) bf16 ready); wait at next loop top ----
        unsigned n2 = 2u * t + 2u;
        __syncthreads();
        if (tid == 0) {
            __threadfence();
            unsigned o = atomicAdd(&g_leaf[leaf], 1u);
            if (o == n2 * 8u - 1u) {
                unsigned o2 = atomicAdd(&g_root, 1u);
                if (o2 == n2 * 16u - 1u) atomicExch(&g_release, n2);
            }
        }
    }
}

// ---------------------------------------------------------------------------
// Epilogue: runs BEFORE gru each replay — zero barriers, write outh, split h0.
// ---------------------------------------------------------------------------
__global__ void epilogue(const float* __restrict__ h0, float* __restrict__ dst)
{
    int i = blockIdx.x * blockDim.x + threadIdx.x;
    if (i < HH) dst[i] = h0[i];
    if (i < 512) {
        float2 v = *(const float2*)&h0[i * 2];
        uint32_t hi, lo;
        split2(v, hi, lo);
        g_h0h[i] = hi;
        g_h0l[i] = lo;
    }
    if (i < 16) g_leaf[i] = 0;
    if (i == 16) g_root = 0;
    if (i == 17) g_release = 0;
}

// ---------------------------------------------------------------------------
extern "C" void kernel_launch(void* const* d_in, const int* in_sizes, int n_in,
                              void* d_out, int out_size)
{
    const float* x = (const float*)d_in[0];
    const unsigned char* reset_raw = (const unsigned char*)d_in[1];
    const float* w_i = (const float*)d_in[2];
    const float* w_h = (const float*)d_in[3];
    const float* b = (const float*)d_in[4];
    const float* h0 = (const float*)d_in[5];

    float* out0 = (float*)d_out;
    float* out1 = out0 + (size_t)NB * TT * HH;
    float* outh = out1 + (size_t)NB * TT * HH;

    cudaFuncSetAttribute(gru_persistent,
                         cudaFuncAttributeMaxDynamicSharedMemorySize, SMEM_GRU2);

    // 0) reset masks + split-precision conversion
    prep_reset<<<1, 512>>>(reset_raw);
    conv_x<<<(NB * TT * DD + 255) / 256, 256>>>(x);
    conv_w<<<(DD * GG + 255) / 256, 256>>>(w_i);

    // 1) gates = x @ w_i + b via mma.sync bf16 (split precision, f32 accum)
    {
        dim3 grid(GG / 128, (NB * TT) / 128);
        mma_gates<<<grid, 256>>>(b);
    }

    // 2) barrier state reset + third output + h0 bf16 split
    epilogue<<<1, 1024>>>(h0, outh);

    // 3) full recurrence in ONE persistent kernel
    gru_persistent<<<NCTA, NTHR, SMEM_GRU2>>>(w_h, h0, out0, out1);
}

// round 16
// speedup vs baseline: 1.9716x; 1.0387x over previous
#include <cuda_runtime.h>
#include <cuda_bf16.h>
#include <cstdint>

// Problem constants
#define NB 32      // batch
#define TT 512     // time steps
#define DD 512     // input dim
#define HH 1024    // hidden dim
#define GG 3072    // 3*H

#define NCTA 128   // persistent grid
#define NTHR 512

// Scratch (module-load allocated; no runtime alloc)
__device__ float g_gates[(size_t)NB * TT * GG];  // 16384 x 3072
__device__ float g_zr[NB * 2 * HH];              // z region used (cols 0..1023)
__device__ unsigned g_rmask[TT];                 // per-step reset bitmasks

// bf16 hi/lo exchange buffers (uint32 = packed bf16 col-pair)
__device__ uint32_t g_hh[NB * 512];   // h(t) hi
__device__ uint32_t g_hl[NB * 512];   // h(t) lo
__device__ uint32_t g_rhh[NB * 512];  // rh hi
__device__ uint32_t g_rhl[NB * 512];  // rh lo
__device__ uint32_t g_h0h[512];       // h0 hi
__device__ uint32_t g_h0l[512];       // h0 lo

// split-precision bf16 operands for the gates GEMM
__device__ __nv_bfloat16 g_xhi[(size_t)NB * TT * DD];
__device__ __nv_bfloat16 g_xlo[(size_t)NB * TT * DD];
__device__ __nv_bfloat16 g_whi[(size_t)GG * DD];   // transposed [n][k]
__device__ __nv_bfloat16 g_wlo[(size_t)GG * DD];

// Hierarchical barrier state (zeroed by epilogue BEFORE gru each replay)
__device__ unsigned g_leaf[16];
__device__ unsigned g_root;
__device__ unsigned g_release;

__device__ __forceinline__ uint32_t smem_u32(const void* p)
{
    uint32_t a;
    asm("{ .reg .u64 t; cvta.to.shared.u64 t, %1; cvt.u32.u64 %0, t; }"
        : "=r"(a) : "l"(p));
    return a;
}

// ldmatrix x4 / x2 (8x8 b16 tiles)
#define LDSM_X4(r, a) \
    asm volatile("ldmatrix.sync.aligned.m8n8.x4.shared.b16 {%0,%1,%2,%3}, [%4];" \
        : "=r"((r)[0]), "=r"((r)[1]), "=r"((r)[2]), "=r"((r)[3]) : "r"(a))
#define LDSM_X2(r, a) \
    asm volatile("ldmatrix.sync.aligned.m8n8.x2.shared.b16 {%0,%1}, [%2];" \
        : "=r"((r)[0]), "=r"((r)[1]) : "r"(a))

// bf16 m16n8k16 mma, f32 accum
#define MMA_BF16(c, a, b0, b1) \
    asm volatile("mma.sync.aligned.m16n8k16.row.col.f32.bf16.bf16.f32 " \
        "{%0,%1,%2,%3}, {%4,%5,%6,%7}, {%8,%9}, {%0,%1,%2,%3};" \
        : "+f"((c)[0]), "+f"((c)[1]), "+f"((c)[2]), "+f"((c)[3]) \
        : "r"((a)[0]), "r"((a)[1]), "r"((a)[2]), "r"((a)[3]), "r"(b0), "r"(b1))

// cp.async 8-byte copy gmem -> smem
#define CP_ASYNC8(s, g) \
    asm volatile("cp.async.ca.shared.global [%0], [%1], 8;" \
        :: "r"(s), "l"(g) : "memory")
#define CP_COMMIT() asm volatile("cp.async.commit_group;" ::: "memory")
#define CP_WAIT0()  asm volatile("cp.async.wait_group 0;" ::: "memory")

// split float2 -> packed bf16 hi/lo uint32s
__device__ __forceinline__ void split2(float2 v, uint32_t& hi, uint32_t& lo)
{
    __nv_bfloat162 h2 = __floats2bfloat162_rn(v.x, v.y);
    float2 hf = __bfloat1622float2(h2);
    __nv_bfloat162 l2 = __floats2bfloat162_rn(v.x - hf.x, v.y - hf.y);
    hi = *(uint32_t*)&h2;
    lo = *(uint32_t*)&l2;
}

__device__ __forceinline__ float2 join2(uint32_t hi, uint32_t lo)
{
    float2 h = __bfloat1622float2(*(__nv_bfloat162*)&hi);
    float2 l = __bfloat1622float2(*(__nv_bfloat162*)&lo);
    return make_float2(h.x + l.x, h.y + l.y);
}

// ---------------------------------------------------------------------------
// Prep: detect reset dtype (bool8 vs int32), build per-step bitmasks.
// ---------------------------------------------------------------------------
__global__ void prep_reset(const unsigned char* __restrict__ raw)
{
    __shared__ int s_bool8;
    int tid = threadIdx.x;
    if (tid == 0) s_bool8 = 0;
    __syncthreads();
    for (int i = tid; i < 4096; i += blockDim.x)
        if ((i & 3) != 0 && raw[i] != 0) s_bool8 = 1;
    __syncthreads();
    bool b8 = (s_bool8 != 0);
    const int* r32 = (const int*)raw;
    for (int t = tid; t < TT; t += blockDim.x) {
        unsigned m = 0;
        for (int b = 0; b < NB; b++) {
            bool rv = b8 ? (raw[b * TT + t] != 0) : (r32[b * TT + t] != 0);
            if (rv) m |= (1u << b);
        }
        if (t == 0) m = 0xFFFFFFFFu;
        g_rmask[t] = m;
    }
}

// ---------------------------------------------------------------------------
// Split-precision conversion kernels (gates GEMM inputs)
// ---------------------------------------------------------------------------
__global__ void conv_x(const float* __restrict__ x)
{
    int i = blockIdx.x * blockDim.x + threadIdx.x;
    if (i < NB * TT * DD) {
        float v = x[i];
        __nv_bfloat16 h = __float2bfloat16(v);
        g_xhi[i] = h;
        g_xlo[i] = __float2bfloat16(v - __bfloat162float(h));
    }
}

__global__ void conv_w(const float* __restrict__ w)
{
    int i = blockIdx.x * blockDim.x + threadIdx.x;
    if (i < DD * GG) {
        int k = i / GG;
        int n = i % GG;
        float v = w[i];
        __nv_bfloat16 h = __float2bfloat16(v);
        g_whi[(size_t)n * DD + k] = h;
        g_wlo[(size_t)n * DD + k] = __float2bfloat16(v - __bfloat162float(h));
    }
}

// ---------------------------------------------------------------------------
// Tensor-core gates GEMM (unchanged from R10 — validated, 435us)
// ---------------------------------------------------------------------------
#define ASTR 40

__global__ __launch_bounds__(256) void mma_gates(const float* __restrict__ bias)
{
    __shared__ __nv_bfloat16 sAh[128][ASTR];
    __shared__ __nv_bfloat16 sAl[128][ASTR];
    __shared__ __nv_bfloat16 sBh[128][ASTR];
    __shared__ __nv_bfloat16 sBl[128][ASTR];

    const int tid = threadIdx.x;
    const int lane = tid & 31;
    const int wid = tid >> 5;
    const int wm = wid & 1;
    const int wn = wid >> 1;
    const int bn = blockIdx.x * 128;
    const int bm = blockIdx.y * 128;

    float c[4][4][4];
#pragma unroll
    for (int i = 0; i < 4; i++)
#pragma unroll
        for (int j = 0; j < 4; j++)
#pragma unroll
            for (int q = 0; q < 4; q++) c[i][j][q] = 0.0f;

    const int a_row = wm * 64 + (lane & 7) + ((lane >> 3) & 1) * 8;
    const int a_col = ((lane >> 4) & 1) * 8;
    const int b_row = wn * 32 + (lane & 7) + ((lane >> 4) & 1) * 8;
    const int b_col = ((lane >> 3) & 1) * 8;

    for (int kc = 0; kc < 16; kc++) {
        for (int i = tid; i < 512; i += 256) {
            int row = i >> 2;
            int c8 = (i & 3) * 8;
            size_t ga = (size_t)(bm + row) * DD + kc * 32 + c8;
            size_t gb = (size_t)(bn + row) * DD + kc * 32 + c8;
            *(uint4*)&sAh[row][c8] = *(const uint4*)&g_xhi[ga];
            *(uint4*)&sAl[row][c8] = *(const uint4*)&g_xlo[ga];
            *(uint4*)&sBh[row][c8] = *(const uint4*)&g_whi[gb];
            *(uint4*)&sBl[row][c8] = *(const uint4*)&g_wlo[gb];
        }
        __syncthreads();

#pragma unroll
        for (int ks = 0; ks < 2; ks++) {
            const int k0 = ks * 16;
            uint32_t ah[4][4], al[4][4], bh[2][4], bl[2][4];
#pragma unroll
            for (int mi = 0; mi < 4; mi++) {
                uint32_t adr = smem_u32(&sAh[a_row + mi * 16][k0 + a_col]);
                LDSM_X4(ah[mi], adr);
                adr = smem_u32(&sAl[a_row + mi * 16][k0 + a_col]);
                LDSM_X4(al[mi], adr);
            }
#pragma unroll
            for (int j = 0; j < 2; j++) {
                uint32_t adr = smem_u32(&sBh[b_row + j * 16][k0 + b_col]);
                LDSM_X4(bh[j], adr);
                adr = smem_u32(&sBl[b_row + j * 16][k0 + b_col]);
                LDSM_X4(bl[j], adr);
            }
#pragma unroll
            for (int mi = 0; mi < 4; mi++) {
#pragma unroll
                for (int nj = 0; nj < 4; nj++) {
                    int j = nj >> 1, p = (nj & 1) * 2;
                    MMA_BF16(c[mi][nj], ah[mi], bh[j][p], bh[j][p + 1]);
                    MMA_BF16(c[mi][nj], ah[mi], bl[j][p], bl[j][p + 1]);
                    MMA_BF16(c[mi][nj], al[mi], bh[j][p], bh[j][p + 1]);
                }
            }
        }
        __syncthreads();
    }

#pragma unroll
    for (int mi = 0; mi < 4; mi++) {
#pragma unroll
        for (int nj = 0; nj < 4; nj++) {
            int r = bm + wm * 64 + mi * 16 + (lane >> 2);
            int cn = bn + wn * 32 + nj * 8 + (lane & 3) * 2;
            float b0 = bias[cn], b1 = bias[cn + 1];
            float2 v0 = make_float2(c[mi][nj][0] + b0, c[mi][nj][1] + b1);
            float2 v1 = make_float2(c[mi][nj][2] + b0, c[mi][nj][3] + b1);
            *(float2*)&g_gates[(size_t)r * GG + cn] = v0;
            *(float2*)&g_gates[(size_t)(r + 8) * GG + cn] = v1;
        }
    }
}

extern __shared__ float dsm[];

// ---------------------------------------------------------------------------
// Persistent recurrence kernel v10 = v9 + cp.async staging + reset-row
// pre-staging before barrier2 wait + barrier1 arrive-early stash overlap.
// ---------------------------------------------------------------------------
#define HSTR 2064
#define OFF_WH 0
#define OFF_WL 49536
#define OFF_HH 99072
#define OFF_HL 165120
#define OFF_RED 231168
#define SMEM_GRU2 (OFF_RED + 1024)   // 232192 <= 232448 cap
#define DLT (OFF_HL - OFF_HH)

__global__ __launch_bounds__(NTHR, 1) void gru_persistent(
    const float* __restrict__ w_h, const float* __restrict__ h0,
    float* out0, float* __restrict__ out1)
{
    char* sm = (char*)dsm;
    float4* sred = (float4*)(sm + OFF_RED);   // [mi*32 + lane]

    const int x = blockIdx.x;
    const int tid = threadIdx.x;
    const int lane = tid & 31;
    const int wid = tid >> 5;
    const int leaf = x & 15;

    // ---- one-time weight preload + split into sWh/sWl ----
    for (int i = tid; i < 24 * 1024; i += NTHR) {
        int c = i >> 10, k = i & 1023;
        int gcol = (c < 16) ? (x * 16 + c) : (2048 + x * 8 + (c - 16));
        float v = w_h[(size_t)k * GG + gcol];
        __nv_bfloat16 h = __float2bfloat16(v);
        __nv_bfloat16 l = __float2bfloat16(v - __bfloat162float(h));
        *(__nv_bfloat16*)(sm + OFF_WH + c * HSTR + 2 * k) = h;
        *(__nv_bfloat16*)(sm + OFF_WL + c * HSTR + 2 * k) = l;
    }
    __syncthreads();

    // warp roles: phase1 (mi, nh); phase2 (mi, kq) — same bit for nh/kq
    const int mi = wid & 1;
    const int sp = (wid >> 1) & 1;     // nh in phase1, kq in phase2

    // A ldmatrix base (validated fragment pattern)
    uint32_t aAh = smem_u32(sm + OFF_HH
        + (mi * 16 + (lane & 7) + ((lane >> 3) & 1) * 8) * HSTR
        + ((lane >> 4) & 1) * 16);
    uint32_t aAl = aAh + DLT;

    // phase1 B (x2): rows = local zr cols nh*8..+8
    uint32_t aB1h = smem_u32(sm + OFF_WH
        + (sp * 8 + (lane & 7)) * HSTR + ((lane >> 3) & 1) * 16);
    uint32_t aB1l = aB1h + (OFF_WL - OFF_WH);

    // phase2 B (x2): rows = W rows 16..23 (a-cols), k offset by kq half
    uint32_t aB2h = smem_u32(sm + OFF_WH
        + (16 + (lane & 7)) * HSTR + ((lane >> 3) & 1) * 16) + sp * 1024;
    uint32_t aB2l = aB2h + (OFF_WL - OFF_WH);
    uint32_t aA2h = aAh + sp * 1024;
    uint32_t aA2l = aAl + sp * 1024;

    const int frow = lane >> 2;
    const int fcol = (lane & 3) * 2;

    const uint32_t sHHb = smem_u32(sm + OFF_HH);

    const uint2* hh2 = (const uint2*)g_hh;
    const uint2* hl2 = (const uint2*)g_hl;
    const uint2* rhh2 = (const uint2*)g_rhh;
    const uint2* rhl2 = (const uint2*)g_rhl;
    const uint2* h0h2 = (const uint2*)g_h0h;
    const uint2* h0l2 = (const uint2*)g_h0l;

    for (int t = 0; t < TT; t++) {
        unsigned rm = g_rmask[t];

        // ---- prefetch gates for this step ----
        float2 gx1[2], gx2[2];
        if (wid < 4) {
            int b0 = mi * 16 + frow;
#pragma unroll
            for (int hh = 0; hh < 2; hh++) {
                size_t grow = ((size_t)(b0 + hh * 8) * TT + t) * GG;
                gx1[hh] = *(const float2*)&g_gates[grow + x * 16 + sp * 8 + fcol];
                if (wid < 2)
                    gx2[hh] = *(const float2*)&g_gates[grow + 2048 + x * 8 + fcol];
            }
        }

        // ---- pre-stage reset rows (h0 — no dependency on h(t-1)) ----
        for (int i = tid; i < 8192; i += NTHR) {
            int b = i >> 8, k4 = i & 255;
            if ((rm >> b) & 1u) {
                uint32_t s = sHHb + b * HSTR + k4 * 8;
                CP_ASYNC8(s, &h0h2[k4]);
                CP_ASYNC8(s + DLT, &h0l2[k4]);
            }
        }
        CP_COMMIT();

        // ---- wait for barrier 2 of previous step (h(t-1) bf16 ready) ----
        if (t > 0) {
            unsigned n = 2u * t;
            if (tid == 0) {
                while (*(volatile unsigned*)&g_release < n) __nanosleep(32);
                __threadfence();
            }
            __syncthreads();
        }

        // ---- stage non-reset rows (cp.async) ----
        for (int i = tid; i < 8192; i += NTHR) {
            int b = i >> 8, k4 = i & 255;
            if (!((rm >> b) & 1u)) {
                uint32_t s = sHHb + b * HSTR + k4 * 8;
                CP_ASYNC8(s, &hh2[b * 256 + k4]);
                CP_ASYNC8(s + DLT, &hl2[b * 256 + k4]);
            }
        }
        CP_COMMIT();
        CP_WAIT0();
        __syncthreads();

        // ---- phase1 MMA: 4 warps (mi x nh), full k, no reduction ----
        if (wid < 4) {
            float acc[3][4];
#pragma unroll
            for (int q = 0; q < 3; q++)
#pragma unroll
                for (int e = 0; e < 4; e++) acc[q][e] = 0.0f;
            uint32_t pAh = aAh, pAl = aAl, pBh = aB1h, pBl = aB1l;
#pragma unroll 4
            for (int ks = 0; ks < 64; ks++) {
                uint32_t Ah[4], Al[4], Bh[2], Bl[2];
                LDSM_X4(Ah, pAh); LDSM_X4(Al, pAl);
                LDSM_X2(Bh, pBh); LDSM_X2(Bl, pBl);
                MMA_BF16(acc[0], Ah, Bh[0], Bh[1]);
                MMA_BF16(acc[1], Ah, Bl[0], Bl[1]);
                MMA_BF16(acc[2], Al, Bh[0], Bh[1]);
                pAh += 32; pAl += 32; pBh += 32; pBl += 32;
            }
            float c0 = acc[0][0] + acc[1][0] + acc[2][0];
            float c1 = acc[0][1] + acc[1][1] + acc[2][1];
            float c2 = acc[0][2] + acc[1][2] + acc[2][2];
            float c3 = acc[0][3] + acc[1][3] + acc[2][3];
            float2 s0, s1;
            s0.x = 1.0f / (1.0f + __expf(-(gx1[0].x + c0)));
            s0.y = 1.0f / (1.0f + __expf(-(gx1[0].y + c1)));
            s1.x = 1.0f / (1.0f + __expf(-(gx1[1].x + c2)));
            s1.y = 1.0f / (1.0f + __expf(-(gx1[1].y + c3)));
            int b0 = mi * 16 + frow;
            if (x < 64) {
                int col = x * 16 + sp * 8 + fcol;
                *(float2*)&g_zr[b0 * 2048 + col] = s0;
                *(float2*)&g_zr[(b0 + 8) * 2048 + col] = s1;
            } else {
                int col = (x - 64) * 16 + sp * 8 + fcol;
                int kp = col >> 1;
#pragma unroll
                for (int hh = 0; hh < 2; hh++) {
                    int b = b0 + hh * 8;
                    float2 rr = hh ? s1 : s0;
                    uint32_t hhi = *(uint32_t*)(sm + OFF_HH + b * HSTR + col * 2);
                    uint32_t hlo = *(uint32_t*)(sm + OFF_HL + b * HSTR + col * 2);
                    float2 hf = join2(hhi, hlo);
                    float2 rh = make_float2(rr.x * hf.x, rr.y * hf.y);
                    uint32_t ohi, olo;
                    split2(rh, ohi, olo);
                    g_rhh[b * 512 + kp] = ohi;
                    g_rhl[b * 512 + kp] = olo;
                }
            }
        }

        // ---- barrier 1: arrive early, stash hw (local) during wait ----
        unsigned n1 = 2u * t + 1u;
        __syncthreads();
        if (tid == 0) {
            __threadfence();
            unsigned o = atomicAdd(&g_leaf[leaf], 1u);
            if (o == n1 * 8u - 1u) {
                unsigned o2 = atomicAdd(&g_root, 1u);
                if (o2 == n1 * 16u - 1u) atomicExch(&g_release, n1);
            }
        }
        // overlap: stash h(t-1) at own a-cols from local smem
        float2 hw[2];
        if (wid < 2) {
            int col = x * 8 + fcol;
#pragma unroll
            for (int hh = 0; hh < 2; hh++) {
                int b = mi * 16 + frow + hh * 8;
                uint32_t hhi = *(uint32_t*)(sm + OFF_HH + b * HSTR + col * 2);
                uint32_t hlo = *(uint32_t*)(sm + OFF_HL + b * HSTR + col * 2);
                hw[hh] = join2(hhi, hlo);
            }
        }
        if (tid == 0) {
            while (*(volatile unsigned*)&g_release < n1) __nanosleep(32);
            __threadfence();
        }
        __syncthreads();

        // ---- z read + restage rh (cp.async) ----
        float2 zz[2];
        if (wid < 2) {
            int col = x * 8 + fcol;
#pragma unroll
            for (int hh = 0; hh < 2; hh++) {
                int b = mi * 16 + frow + hh * 8;
                zz[hh] = __ldcg((const float2*)&g_zr[b * 2048 + col]);
            }
        }
        for (int i = tid; i < 8192; i += NTHR) {
            int b = i >> 8, k4 = i & 255;
            uint32_t s = sHHb + b * HSTR + k4 * 8;
            CP_ASYNC8(s, &rhh2[b * 256 + k4]);
            CP_ASYNC8(s + DLT, &rhl2[b * 256 + k4]);
        }
        CP_COMMIT();
        CP_WAIT0();
        __syncthreads();

        // ---- phase2 MMA: 4 warps (mi x kq), half k each ----
        float cc[4] = {0.f, 0.f, 0.f, 0.f};
        if (wid < 4) {
            float ac2[3][4];
#pragma unroll
            for (int q = 0; q < 3; q++)
#pragma unroll
                for (int e = 0; e < 4; e++) ac2[q][e] = 0.0f;
            uint32_t pAh = aA2h, pAl = aA2l, pBh = aB2h, pBl = aB2l;
#pragma unroll 4
            for (int ks = 0; ks < 32; ks++) {
                uint32_t Ah[4], Al[4], Bh[2], Bl[2];
                LDSM_X4(Ah, pAh); LDSM_X4(Al, pAl);
                LDSM_X2(Bh, pBh); LDSM_X2(Bl, pBl);
                MMA_BF16(ac2[0], Ah, Bh[0], Bh[1]);
                MMA_BF16(ac2[1], Ah, Bl[0], Bl[1]);
                MMA_BF16(ac2[2], Al, Bh[0], Bh[1]);
                pAh += 32; pAl += 32; pBh += 32; pBl += 32;
            }
#pragma unroll
            for (int e = 0; e < 4; e++)
                cc[e] = ac2[0][e] + ac2[1][e] + ac2[2][e];
        }
        // cross-warp k reduction: kq==1 warps (wid 2,3) publish, kq==0 fold
        if (wid >= 2 && wid < 4)
            sred[mi * 32 + lane] = make_float4(cc[0], cc[1], cc[2], cc[3]);
        __syncthreads();
        if (wid < 2) {
            float4 p = sred[mi * 32 + lane];
            cc[0] += p.x; cc[1] += p.y; cc[2] += p.z; cc[3] += p.w;

            int col = x * 8 + fcol;
            int kp = col >> 1;
#pragma unroll
            for (int hh = 0; hh < 2; hh++) {
                int b = mi * 16 + frow + hh * 8;
                float a0 = tanhf(gx2[hh].x + cc[hh * 2 + 0]);
                float a1 = tanhf(gx2[hh].y + cc[hh * 2 + 1]);
                float2 hn;
                hn.x = (1.0f - zz[hh].x) * hw[hh].x + zz[hh].x * a0;
                hn.y = (1.0f - zz[hh].y) * hw[hh].y + zz[hh].y * a1;
                size_t o = ((size_t)b * TT + t) * HH + col;
                *(float2*)&out0[o] = hn;
                *(float2*)&out1[o] = hn;
                uint32_t nhi, nlo;
                split2(hn, nhi, nlo);
                g_hh[b * 512 + kp] = nhi;
                g_hl[b * 512 + kp] = nlo;
            }
        }

        // ---- barrier 2 arrive (h(t) bf16 ready); wait at next loop top ----
        unsigned n2 = 2u * t + 2u;
        __syncthreads();
        if (tid == 0) {
            __threadfence();
            unsigned o = atomicAdd(&g_leaf[leaf], 1u);
            if (o == n2 * 8u - 1u) {
                unsigned o2 = atomicAdd(&g_root, 1u);
                if (o2 == n2 * 16u - 1u) atomicExch(&g_release, n2);
            }
        }
    }
}

// ---------------------------------------------------------------------------
// Epilogue: runs BEFORE gru each replay — zero barriers, write outh, split h0.
// ---------------------------------------------------------------------------
__global__ void epilogue(const float* __restrict__ h0, float* __restrict__ dst)
{
    int i = blockIdx.x * blockDim.x + threadIdx.x;
    if (i < HH) dst[i] = h0[i];
    if (i < 512) {
        float2 v = *(const float2*)&h0[i * 2];
        uint32_t hi, lo;
        split2(v, hi, lo);
        g_h0h[i] = hi;
        g_h0l[i] = lo;
    }
    if (i < 16) g_leaf[i] = 0;
    if (i == 16) g_root = 0;
    if (i == 17) g_release = 0;
}

// ---------------------------------------------------------------------------
extern "C" void kernel_launch(void* const* d_in, const int* in_sizes, int n_in,
                              void* d_out, int out_size)
{
    const float* x = (const float*)d_in[0];
    const unsigned char* reset_raw = (const unsigned char*)d_in[1];
    const float* w_i = (const float*)d_in[2];
    const float* w_h = (const float*)d_in[3];
    const float* b = (const float*)d_in[4];
    const float* h0 = (const float*)d_in[5];

    float* out0 = (float*)d_out;
    float* out1 = out0 + (size_t)NB * TT * HH;
    float* outh = out1 + (size_t)NB * TT * HH;

    cudaFuncSetAttribute(gru_persistent,
                         cudaFuncAttributeMaxDynamicSharedMemorySize, SMEM_GRU2);

    // 0) reset masks + split-precision conversion
    prep_reset<<<1, 512>>>(reset_raw);
    conv_x<<<(NB * TT * DD + 255) / 256, 256>>>(x);
    conv_w<<<(DD * GG + 255) / 256, 256>>>(w_i);

    // 1) gates = x @ w_i + b via mma.sync bf16 (split precision, f32 accum)
    {
        dim3 grid(GG / 128, (NB * TT) / 128);
        mma_gates<<<grid, 256>>>(b);
    }

    // 2) barrier state reset + third output + h0 bf16 split
    epilogue<<<1, 1024>>>(h0, outh);

    // 3) full recurrence in ONE persistent kernel
    gru_persistent<<<NCTA, NTHR, SMEM_GRU2>>>(w_h, h0, out0, out1);
}